// round 1
// baseline (speedup 1.0000x reference)
#include <cuda_runtime.h>
#include <cuda_bf16.h>
#include <cstdint>

// Problem dims
#define TT 512      // timesteps
#define IDIM 512    // input dim
#define H 1024      // hidden
#define G 4096      // 4*H gates
#define LDIM 512    // attention length
#define NB 128      // persistent blocks (<= 148 SMs -> co-resident)
#define NT 256      // threads per block (8 warps)
#define RPB 32      // g_dc rows per block (G/NB)

// ---------------- device scratch (no allocations allowed) ----------------
__device__ __align__(16) float d_pre[(size_t)G * TT];     // pre_ih[r][t] = W_ih_e@x_t + b_ih_e + b_hh_e   (8MB)
__device__ __align__(16) float d_Wcomb[(size_t)G * H];    // W_ih_d[:,H:] + W_hh_d                         (16MB)
__device__ __align__(16) float d_bd[G];                   // b_ih_d + b_hh_d
__device__ __align__(16) float d_eh[2][H];                // ping-pong encoder hidden
__device__ __align__(16) float d_dh[2][H];                // ping-pong decoder hidden
__device__ __align__(16) float d_aw[LDIM];                // attention weights (persistent state)
__device__ __align__(16) float d_gdc[G];                  // per-step W_comb@dh + b_d
__device__ float d_s;                                     // softmax scalar aw[t]
__device__ unsigned c_eh, c_gdc, c_s, c_barA;             // monotonic counters
__device__ unsigned c_barR;                               // barrier release epoch

__device__ __forceinline__ float sigf(float x) { return 1.f / (1.f + __expf(-x)); }

__device__ __forceinline__ void wait_ge(const unsigned* p, unsigned tgt) {
  while (*(volatile const unsigned*)p < tgt) {}
  __threadfence();
}

// Warp-cooperative: 4 simultaneous 1024-dots (rows r0 + i*rstep of W, pitch floats/row)
// against vector v (read via L2 since it's produced by other SMs).
__device__ __forceinline__ void warp_dot4(const float* __restrict__ W, int pitch,
                                          int r0, int rstep,
                                          const float* __restrict__ v,
                                          int lane, float acc[4]) {
  const float4* p0 = reinterpret_cast<const float4*>(W + (size_t)r0 * pitch);
  const float4* p1 = reinterpret_cast<const float4*>(W + (size_t)(r0 + rstep) * pitch);
  const float4* p2 = reinterpret_cast<const float4*>(W + (size_t)(r0 + 2 * rstep) * pitch);
  const float4* p3 = reinterpret_cast<const float4*>(W + (size_t)(r0 + 3 * rstep) * pitch);
  const float4* v4 = reinterpret_cast<const float4*>(v);
  float a0 = 0.f, a1 = 0.f, a2 = 0.f, a3 = 0.f;
#pragma unroll
  for (int c = 0; c < 8; ++c) {
    int idx = c * 32 + lane;
    float4 vv = __ldcg(v4 + idx);
    float4 q0 = __ldg(p0 + idx);
    float4 q1 = __ldg(p1 + idx);
    float4 q2 = __ldg(p2 + idx);
    float4 q3 = __ldg(p3 + idx);
    a0 += q0.x * vv.x + q0.y * vv.y + q0.z * vv.z + q0.w * vv.w;
    a1 += q1.x * vv.x + q1.y * vv.y + q1.z * vv.z + q1.w * vv.w;
    a2 += q2.x * vv.x + q2.y * vv.y + q2.z * vv.z + q2.w * vv.w;
    a3 += q3.x * vv.x + q3.y * vv.y + q3.z * vv.z + q3.w * vv.w;
  }
#pragma unroll
  for (int o = 16; o; o >>= 1) {
    a0 += __shfl_xor_sync(0xffffffffu, a0, o);
    a1 += __shfl_xor_sync(0xffffffffu, a1, o);
    a2 += __shfl_xor_sync(0xffffffffu, a2, o);
    a3 += __shfl_xor_sync(0xffffffffu, a3, o);
  }
  acc[0] = a0; acc[1] = a1; acc[2] = a2; acc[3] = a3;
}

// ---------------- init: zero state + counters ----------------
__global__ void init_state() {
  int i = blockIdx.x * blockDim.x + threadIdx.x;
  if (i == 0) { c_eh = 0; c_gdc = 0; c_s = 0; c_barA = 0; c_barR = 0; }
  if (i < H) { d_eh[0][i] = 0.f; d_eh[1][i] = 0.f; d_dh[0][i] = 0.f; d_dh[1][i] = 0.f; }
  if (i < LDIM) d_aw[i] = 0.f;
}

// ---------------- fold decoder weights: W_comb = W_ih_d[:,H:] + W_hh_d ----------------
__global__ void build_comb(const float* __restrict__ Wihd, const float* __restrict__ Whhd,
                           const float* __restrict__ bihd, const float* __restrict__ bhhd) {
  const int n = G * H;
  for (int i = blockIdx.x * blockDim.x + threadIdx.x; i < n; i += gridDim.x * blockDim.x) {
    int r = i >> 10, k = i & (H - 1);
    d_Wcomb[i] = Wihd[(size_t)r * (2 * H) + H + k] + Whhd[i];
  }
  for (int i = blockIdx.x * blockDim.x + threadIdx.x; i < G; i += gridDim.x * blockDim.x)
    d_bd[i] = bihd[i] + bhhd[i];
}

// ---------------- precompute pre_ih = W_ih_e @ x_t + biases, tiled fp32 GEMM ----------------
// C[r][t] = sum_k A[r][k] * B[t][k];  A=[4096,512], B=[512,512]
#define BM 64
#define BN 64
#define BK 32
__global__ void __launch_bounds__(256) gemm_pre(const float* __restrict__ A,
                                                const float* __restrict__ B,
                                                const float* __restrict__ bih,
                                                const float* __restrict__ bhh) {
  __shared__ float As[BK][BM + 1];
  __shared__ float Bs[BK][BN + 1];
  int tid = threadIdx.x;
  int r0 = blockIdx.y * BM;
  int t0 = blockIdx.x * BN;
  int tx = tid & 15, ty = tid >> 4;
  float acc[4][4] = {};
  for (int k0 = 0; k0 < IDIM; k0 += BK) {
#pragma unroll
    for (int i = 0; i < 8; ++i) {
      int lin = tid + i * 256;
      int m = lin >> 5, kk = lin & 31;
      As[kk][m] = A[(size_t)(r0 + m) * IDIM + k0 + kk];
      Bs[kk][m] = B[(size_t)(t0 + m) * IDIM + k0 + kk];
    }
    __syncthreads();
#pragma unroll
    for (int kk = 0; kk < BK; ++kk) {
      float a[4], bv[4];
#pragma unroll
      for (int j = 0; j < 4; ++j) { a[j] = As[kk][ty * 4 + j]; bv[j] = Bs[kk][tx * 4 + j]; }
#pragma unroll
      for (int i2 = 0; i2 < 4; ++i2)
#pragma unroll
        for (int j = 0; j < 4; ++j) acc[i2][j] += a[i2] * bv[j];
    }
    __syncthreads();
  }
#pragma unroll
  for (int i2 = 0; i2 < 4; ++i2) {
    int r = r0 + ty * 4 + i2;
    float bias = bih[r] + bhh[r];
#pragma unroll
    for (int j = 0; j < 4; ++j)
      d_pre[(size_t)r * TT + (t0 + tx * 4 + j)] = acc[i2][j] + bias;
  }
}

// ---------------- persistent sequential LSTM kernel ----------------
__global__ void __launch_bounds__(NT, 1)
lstm_persist(const float* __restrict__ Whh_e,
             const float* __restrict__ Wihd,    // for W_A = W_ih_d[:, :H], row pitch 2H
             const float* __restrict__ Wattn,
             const float* __restrict__ battn,
             const float* __restrict__ Wout,
             const float* __restrict__ bout,
             float* __restrict__ out) {
  const int b = blockIdx.x;
  const int tid = threadIdx.x;
  const int w = tid >> 5;
  const int lane = tid & 31;
  const int u = b * 8 + w;        // hidden unit owned by this warp (encoder + decoder)
  const int r0 = b * RPB + w * 4; // g_dc rows owned by this warp

  float ec = 0.f, dc = 0.f;       // cell states live in registers (lane 0 authoritative)

  for (int t = 0; t < TT; ++t) {
    const int rt = t & 1, wt = rt ^ 1;
    const float* ehR = d_eh[rt];
    float*       ehW = d_eh[wt];
    const float* dhR = d_dh[rt];
    float*       dhW = d_dh[wt];

    // ---- Phase 1a: encoder LSTM cell for unit u ----
    {
      float acc[4];
      warp_dot4(Whh_e, H, u, H, ehR, lane, acc);
      if (lane == 0) {
        float gi = acc[0] + d_pre[(size_t)u * TT + t];
        float gf = acc[1] + d_pre[(size_t)(u + H) * TT + t];
        float gg = acc[2] + d_pre[(size_t)(u + 2 * H) * TT + t];
        float go = acc[3] + d_pre[(size_t)(u + 3 * H) * TT + t];
        ec = sigf(gf) * ec + sigf(gi) * tanhf(gg);
        ehW[u] = sigf(go) * tanhf(ec);
        __threadfence();
      }
    }
    __syncthreads();
    if (tid == 0) atomicAdd(&c_eh, 1u);

    // ---- softmax / attention scalar: block NB-1, warp 0 ----
    if (b == NB - 1 && w == 0) {
      wait_ge(&c_eh, (unsigned)NB * (t + 1));
      const float* wr = Wattn + (size_t)t * (2 * H);
      float e = 0.f;
#pragma unroll 4
      for (int k = lane; k < H; k += 32) e += __ldg(wr + k) * __ldcg(ehW + k);
#pragma unroll 4
      for (int k = lane; k < H; k += 32) e += __ldg(wr + H + k) * __ldcg(dhR + k);
#pragma unroll
      for (int o = 16; o; o >>= 1) e += __shfl_xor_sync(0xffffffffu, e, o);
      e += battn[t];
      // softmax over aw with aw[t] replaced by e (owner-only state)
      float vals[16];
      float m = -1e30f;
#pragma unroll
      for (int j = 0; j < 16; ++j) {
        int idx = j * 32 + lane;
        float x = (idx == t) ? e : d_aw[idx];
        vals[j] = x;
        m = fmaxf(m, x);
      }
#pragma unroll
      for (int o = 16; o; o >>= 1) m = fmaxf(m, __shfl_xor_sync(0xffffffffu, m, o));
      float sum = 0.f;
#pragma unroll
      for (int j = 0; j < 16; ++j) { vals[j] = __expf(vals[j] - m); sum += vals[j]; }
#pragma unroll
      for (int o = 16; o; o >>= 1) sum += __shfl_xor_sync(0xffffffffu, sum, o);
      float inv = 1.f / sum;
#pragma unroll
      for (int j = 0; j < 16; ++j) d_aw[j * 32 + lane] = vals[j] * inv;
      if (lane == 0) {
        d_s = __expf(e - m) * inv;
        __threadfence();
        atomicAdd(&c_s, 1u);
      }
    }

    // ---- Phase 1b: g_dc rows (W_comb @ dh_old + b_d) ----
    {
      float acc[4];
      warp_dot4(d_Wcomb, H, r0, 1, dhR, lane, acc);
      if (lane == 0) {
        d_gdc[r0]     = acc[0] + d_bd[r0];
        d_gdc[r0 + 1] = acc[1] + d_bd[r0 + 1];
        d_gdc[r0 + 2] = acc[2] + d_bd[r0 + 2];
        d_gdc[r0 + 3] = acc[3] + d_bd[r0 + 3];
        __threadfence();
      }
    }

    // ---- output for previous step (dh_old is this step's dhR) ----
    if (b == 0 && w == 0 && t > 0) {
      float o = 0.f;
#pragma unroll 4
      for (int k = lane; k < H; k += 32) o += __ldg(Wout + k) * __ldcg(dhR + k);
#pragma unroll
      for (int of = 16; of; of >>= 1) o += __shfl_xor_sync(0xffffffffu, o, of);
      if (lane == 0) out[t - 1] = o + bout[0];
    }

    __syncthreads();
    if (tid == 0) atomicAdd(&c_gdc, 1u);

    // ---- Phase 2: decoder LSTM cell for unit u ----
    {
      // need full eh_new before the dots
      while (*(volatile const unsigned*)&c_eh < (unsigned)NB * (t + 1)) {}
      __threadfence();
      float acc[4];
      warp_dot4(Wihd, 2 * H, u, H, ehW, lane, acc);  // W_A rows inside W_ih_d, pitch 2H
      if (lane == 0) {
        wait_ge(&c_s, (unsigned)(t + 1));
        wait_ge(&c_gdc, (unsigned)NB * (t + 1));
        float s = *(volatile const float*)&d_s;
        float gi = s * acc[0] + __ldcg(&d_gdc[u]);
        float gf = s * acc[1] + __ldcg(&d_gdc[u + H]);
        float gg = s * acc[2] + __ldcg(&d_gdc[u + 2 * H]);
        float go = s * acc[3] + __ldcg(&d_gdc[u + 3 * H]);
        dc = sigf(gf) * dc + sigf(gi) * tanhf(gg);
        dhW[u] = sigf(go) * tanhf(dc);
        __threadfence();
      }
    }

    // ---- end-of-step grid barrier ----
    __syncthreads();
    if (tid == 0) {
      unsigned a = atomicAdd(&c_barA, 1u);
      if (a == (unsigned)NB * (t + 1) - 1u) {
        __threadfence();
        *(volatile unsigned*)&c_barR = (unsigned)(t + 1);
      } else {
        while (*(volatile const unsigned*)&c_barR < (unsigned)(t + 1)) {}
        __threadfence();
      }
    }
    __syncthreads();
  }

  // ---- final output (dh from step T-1 lives in d_dh[0]) ----
  if (b == 0 && w == 0) {
    float o = 0.f;
#pragma unroll 4
    for (int k = lane; k < H; k += 32) o += __ldg(Wout + k) * __ldcg(&d_dh[0][k]);
#pragma unroll
    for (int of = 16; of; of >>= 1) o += __shfl_xor_sync(0xffffffffu, o, of);
    if (lane == 0) out[TT - 1] = o + bout[0];
  }
}

// ---------------- launch ----------------
extern "C" void kernel_launch(void* const* d_in, const int* in_sizes, int n_in,
                              void* d_out, int out_size) {
  const float* input_seq = (const float*)d_in[0];
  // d_in[1] = target_seq (unused by reference)
  const float* W_ih_e = (const float*)d_in[2];
  const float* W_hh_e = (const float*)d_in[3];
  const float* b_ih_e = (const float*)d_in[4];
  const float* b_hh_e = (const float*)d_in[5];
  const float* W_attn = (const float*)d_in[6];
  const float* b_attn = (const float*)d_in[7];
  const float* W_ih_d = (const float*)d_in[8];
  const float* W_hh_d = (const float*)d_in[9];
  const float* b_ih_d = (const float*)d_in[10];
  const float* b_hh_d = (const float*)d_in[11];
  const float* W_out  = (const float*)d_in[12];
  const float* b_out  = (const float*)d_in[13];
  float* out = (float*)d_out;

  init_state<<<8, 256>>>();
  build_comb<<<512, 256>>>(W_ih_d, W_hh_d, b_ih_d, b_hh_d);
  gemm_pre<<<dim3(IDIM / BN, G / BM), 256>>>(W_ih_e, input_seq, b_ih_e, b_hh_e);
  lstm_persist<<<NB, NT>>>(W_hh_e, W_ih_d, W_attn, b_attn, W_out, b_out, out);
}

// round 2
// speedup vs baseline: 2.3684x; 2.3684x over previous
#include <cuda_runtime.h>
#include <cstdint>

#define TT 512      // timesteps
#define IDIM 512    // input dim
#define H 1024      // hidden
#define G 4096      // 4*H
#define NB 128      // persistent blocks
#define NT 256      // threads/block (8 warps)
#define JRES 20     // resident W_A rows per block (of 32)

// ---------------- device scratch ----------------
__device__ __align__(16) float d_pre[(size_t)G * TT];    // W_ih_e@x_t + b_ih_e + b_hh_e
__device__ __align__(16) float d_Wcomb[(size_t)G * H];   // W_ih_d[:,H:] + W_hh_d
__device__ __align__(16) float d_bd[G];                  // b_ih_d + b_hh_d
__device__ __align__(16) float d_eh[2][H];
__device__ __align__(16) float d_dh[2][H];
__device__ unsigned c_eh, c_dh;

__device__ __forceinline__ float sigf(float x) { return 1.f / (1.f + __expf(-x)); }
__device__ __forceinline__ float dot4(float4 a, float4 b) {
  return a.x * b.x + a.y * b.y + a.z * b.z + a.w * b.w;
}
__device__ __forceinline__ float wredsum(float v) {
#pragma unroll
  for (int o = 16; o; o >>= 1) v += __shfl_xor_sync(0xffffffffu, v, o);
  return v;
}
__device__ __forceinline__ float wredmax(float v) {
#pragma unroll
  for (int o = 16; o; o >>= 1) v = fmaxf(v, __shfl_xor_sync(0xffffffffu, v, o));
  return v;
}
__device__ __forceinline__ unsigned ld_acq(const unsigned* p) {
  unsigned v;
  asm volatile("ld.acquire.gpu.global.u32 %0, [%1];" : "=r"(v) : "l"(p) : "memory");
  return v;
}
__device__ __forceinline__ void red_rel(unsigned* p) {
  unsigned one = 1u;
  asm volatile("red.release.gpu.global.add.u32 [%0], %1;" :: "l"(p), "r"(one) : "memory");
}

// ---------------- init ----------------
__global__ void init_state() {
  int i = blockIdx.x * blockDim.x + threadIdx.x;
  if (i == 0) { c_eh = 0; c_dh = 0; }
  if (i < H) { d_eh[0][i] = 0.f; d_eh[1][i] = 0.f; d_dh[0][i] = 0.f; d_dh[1][i] = 0.f; }
}

// ---------------- fold decoder weights ----------------
__global__ void build_comb(const float* __restrict__ Wihd, const float* __restrict__ Whhd,
                           const float* __restrict__ bihd, const float* __restrict__ bhhd) {
  const int n = G * H;
  for (int i = blockIdx.x * blockDim.x + threadIdx.x; i < n; i += gridDim.x * blockDim.x) {
    int r = i >> 10, k = i & (H - 1);
    d_Wcomb[i] = Wihd[(size_t)r * (2 * H) + H + k] + Whhd[i];
  }
  for (int i = blockIdx.x * blockDim.x + threadIdx.x; i < G; i += gridDim.x * blockDim.x)
    d_bd[i] = bihd[i] + bhhd[i];
}

// ---------------- precompute pre[r][t] = W_ih_e@x_t + biases ----------------
#define GBM 128
#define GBN 64
#define GBK 16
__global__ void __launch_bounds__(256) gemm_pre(const float* __restrict__ A,
                                                const float* __restrict__ B,
                                                const float* __restrict__ bih,
                                                const float* __restrict__ bhh) {
  __shared__ float As[GBK][GBM + 4];
  __shared__ float Bs[GBK][GBN + 4];
  const int tid = threadIdx.x;
  const int r0 = blockIdx.y * GBM;
  const int t0 = blockIdx.x * GBN;
  const int tx = tid & 15, ty = tid >> 4;
  float acc[8][4] = {};
  for (int k0 = 0; k0 < IDIM; k0 += GBK) {
#pragma unroll
    for (int i = 0; i < 2; ++i) {
      int lin = tid + i * 256;           // 0..511 -> 512 float4 = 128 rows x 4 f4
      int m = lin >> 2, kq = lin & 3;
      float4 v = __ldg((const float4*)(A + (size_t)(r0 + m) * IDIM + k0) + kq);
      As[kq * 4 + 0][m] = v.x; As[kq * 4 + 1][m] = v.y;
      As[kq * 4 + 2][m] = v.z; As[kq * 4 + 3][m] = v.w;
    }
    {
      int m = tid >> 2, kq = tid & 3;    // 256 f4 = 64 rows x 4 f4
      float4 v = __ldg((const float4*)(B + (size_t)(t0 + m) * IDIM + k0) + kq);
      Bs[kq * 4 + 0][m] = v.x; Bs[kq * 4 + 1][m] = v.y;
      Bs[kq * 4 + 2][m] = v.z; Bs[kq * 4 + 3][m] = v.w;
    }
    __syncthreads();
#pragma unroll
    for (int kk = 0; kk < GBK; ++kk) {
      float a[8], bv[4];
#pragma unroll
      for (int j = 0; j < 8; ++j) a[j] = As[kk][ty * 8 + j];
#pragma unroll
      for (int j = 0; j < 4; ++j) bv[j] = Bs[kk][tx * 4 + j];
#pragma unroll
      for (int i2 = 0; i2 < 8; ++i2)
#pragma unroll
        for (int j = 0; j < 4; ++j) acc[i2][j] += a[i2] * bv[j];
    }
    __syncthreads();
  }
#pragma unroll
  for (int i2 = 0; i2 < 8; ++i2) {
    int r = r0 + ty * 8 + i2;
    float bias = __ldg(bih + r) + __ldg(bhh + r);
#pragma unroll
    for (int j = 0; j < 4; ++j)
      d_pre[(size_t)r * TT + (t0 + tx * 4 + j)] = acc[i2][j] + bias;
  }
}

// ---------------- persistent sequential kernel ----------------
// Shared layout (floats): shWe 32*1024 | shWA JRES*1024 | shEh 1024 | shDh 1024 |
//                         shEn 1024 | shAw 512 | shMs 16
#define SMEM_FLOATS (32 * 1024 + JRES * 1024 + 1024 * 3 + 512 + 16)

__global__ void __launch_bounds__(NT, 1)
lstm_persist(const float* __restrict__ Whh_e,
             const float* __restrict__ Wihd,   // W_A = first H cols, pitch 2H
             const float* __restrict__ Wattn,
             const float* __restrict__ battn,
             const float* __restrict__ Wout,
             const float* __restrict__ bout,
             float* __restrict__ out) {
  extern __shared__ __align__(16) float sh[];
  float* shWe = sh;                         // 32768
  float* shWA = sh + 32 * 1024;             // 20480
  float* shEh = shWA + JRES * 1024;         // 1024
  float* shDh = shEh + 1024;                // 1024
  float* shEn = shDh + 1024;                // 1024
  float* shAw = shEn + 1024;                // 512
  float* shMs = shAw + 512;                 // 16

  const int b = blockIdx.x;
  const int tid = threadIdx.x;
  const int w = tid >> 5;
  const int lane = tid & 31;
  const int u = b * 8 + w;

  // ---- one-time preload of resident weights ----
  for (int i = tid; i < 32 * 256; i += NT) {        // 32 rows x 256 f4
    int row = i >> 8, c4 = i & 255, wv = row >> 2, g = row & 3;
    ((float4*)shWe)[i] =
        __ldg((const float4*)(Whh_e + ((size_t)(b * 8 + wv) + (size_t)g * H) * H) + c4);
  }
  for (int i = tid; i < JRES * 256; i += NT) {      // jj = g*8+w
    int jj = i >> 8, c4 = i & 255, g = jj >> 3, wv = jj & 7;
    ((float4*)shWA)[i] =
        __ldg((const float4*)(Wihd + ((size_t)(b * 8 + wv) + (size_t)g * H) * (2 * H)) + c4);
  }
  for (int i = tid; i < 512; i += NT) shAw[i] = 0.f;

  float bdv[4];
#pragma unroll
  for (int g = 0; g < 4; ++g) bdv[g] = __ldg(&d_bd[u + g * H]);
  const float bout0 = __ldg(bout);

  bool resv[4]; int jbase[4];
#pragma unroll
  for (int g = 0; g < 4; ++g) { int jj = g * 8 + w; resv[g] = (jj < JRES); jbase[g] = jj * 256; }

  float ec = 0.f, dc = 0.f;
  float redB[4] = {0.f, 0.f, 0.f, 0.f};
  __syncthreads();

  for (int t = 0; t < TT; ++t) {
    const int rt = t & 1, wt2 = rt ^ 1;

    // ---- grid barrier: previous step's dh complete ----
    if (tid == 0) {
      unsigned tgt = 1024u * (unsigned)t;
      while (ld_acq(&c_dh) < tgt) __nanosleep(32);
    }
    __syncthreads();

    // ---- stage eh_old, dh_old ----
    ((float4*)shEh)[tid] = __ldcg((const float4*)d_eh[rt] + tid);
    ((float4*)shDh)[tid] = __ldcg((const float4*)d_dh[rt] + tid);
    float pre_g[4];
#pragma unroll
    for (int g = 0; g < 4; ++g) pre_g[g] = __ldg(&d_pre[((size_t)(u + g * H)) * TT + t]);
    __syncthreads();

    float4 ehq[8], dhq[8];
#pragma unroll
    for (int c = 0; c < 8; ++c) {
      ehq[c] = ((const float4*)shEh)[c * 32 + lane];
      dhq[c] = ((const float4*)shDh)[c * 32 + lane];
    }

    // ---- encoder dots (shared-resident weights) -> fastest path to eh release ----
    float aE[4] = {0.f, 0.f, 0.f, 0.f};
#pragma unroll
    for (int c = 0; c < 8; ++c) {
      float4 v = ehq[c];
      int base = c * 32 + lane;
#pragma unroll
      for (int g = 0; g < 4; ++g)
        aE[g] += dot4(((const float4*)shWe)[(w * 4 + g) * 256 + base], v);
    }
#pragma unroll
    for (int g = 0; g < 4; ++g) aE[g] = wredsum(aE[g]);
    if (lane == 0) {
      float gi = aE[0] + pre_g[0], gf = aE[1] + pre_g[1];
      float gg = aE[2] + pre_g[2], go = aE[3] + pre_g[3];
      ec = sigf(gf) * ec + sigf(gi) * tanhf(gg);
      float ehn = sigf(go) * tanhf(ec);
      __stcg(&d_eh[wt2][u], ehn);
      red_rel(&c_eh);
    }

    // ---- W_comb @ dh_old (streamed from L2), own decoder rows ----
    {
      float aB[4] = {0.f, 0.f, 0.f, 0.f};
      const float4* pc = (const float4*)(d_Wcomb + (size_t)u * H);
#pragma unroll
      for (int c = 0; c < 8; ++c) {
        int idx = c * 32 + lane;
        float4 v = dhq[c];
#pragma unroll
        for (int g = 0; g < 4; ++g)
          aB[g] += dot4(__ldg(pc + (size_t)g * (H * H / 4) + idx), v);
      }
#pragma unroll
      for (int g = 0; g < 4; ++g) redB[g] = wredsum(aB[g]);
    }

    // ---- attention dh-half (warp 0, block-private) ----
    if (w == 0) {
      const float4* wr = (const float4*)(Wattn + (size_t)t * (2 * H) + H);
      float e = 0.f;
#pragma unroll
      for (int c = 0; c < 8; ++c) e += dot4(__ldg(wr + c * 32 + lane), dhq[c]);
      e = wredsum(e);
      if (lane == 0) shMs[0] = e;
    }
    // ---- out[t-1] (block 0, warp 1) ----
    if (b == 0 && w == 1 && t > 0) {
      const float4* wo = (const float4*)Wout;
      float o = 0.f;
#pragma unroll
      for (int c = 0; c < 8; ++c) o += dot4(__ldg(wo + c * 32 + lane), dhq[c]);
      o = wredsum(o);
      if (lane == 0) out[t - 1] = o + bout0;
    }

    // ---- wait for all eh_new; stage ----
    if (tid == 0) {
      unsigned tgt = 1024u * (unsigned)(t + 1);
      while (ld_acq(&c_eh) < tgt) __nanosleep(32);
    }
    __syncthreads();
    ((float4*)shEn)[tid] = __ldcg((const float4*)d_eh[wt2] + tid);
    __syncthreads();

    float4 enq[8];
#pragma unroll
    for (int c = 0; c < 8; ++c) enq[c] = ((const float4*)shEn)[c * 32 + lane];

    // ---- W_A @ eh_new (mostly shared-resident) ----
    float aA[4] = {0.f, 0.f, 0.f, 0.f};
#pragma unroll
    for (int g = 0; g < 4; ++g) {
      if (resv[g]) {
#pragma unroll
        for (int c = 0; c < 8; ++c)
          aA[g] += dot4(((const float4*)shWA)[jbase[g] + c * 32 + lane], enq[c]);
      } else {
        const float4* pw = (const float4*)(Wihd + ((size_t)u + (size_t)g * H) * (2 * H));
#pragma unroll
        for (int c = 0; c < 8; ++c)
          aA[g] += dot4(__ldg(pw + c * 32 + lane), enq[c]);
      }
    }

    // ---- attention eh-half + block-private softmax (warp 0) ----
    if (w == 0) {
      const float4* wr = (const float4*)(Wattn + (size_t)t * (2 * H));
      float e2 = 0.f;
#pragma unroll
      for (int c = 0; c < 8; ++c) e2 += dot4(__ldg(wr + c * 32 + lane), enq[c]);
      e2 = wredsum(e2);
      float e = e2 + shMs[0] + __ldg(&battn[t]);
      float vals[16];
      float m = -1e30f;
#pragma unroll
      for (int j = 0; j < 16; ++j) {
        int idx = j * 32 + lane;
        float x = (idx == t) ? e : shAw[idx];
        vals[j] = x;
        m = fmaxf(m, x);
      }
      m = wredmax(m);
      float ssum = 0.f;
#pragma unroll
      for (int j = 0; j < 16; ++j) { vals[j] = __expf(vals[j] - m); ssum += vals[j]; }
      ssum = wredsum(ssum);
      float inv = 1.f / ssum;
#pragma unroll
      for (int j = 0; j < 16; ++j) shAw[j * 32 + lane] = vals[j] * inv;
      if (lane == 0) shMs[1] = __expf(e - m) * inv;
    }
    __syncthreads();
    const float s = shMs[1];
#pragma unroll
    for (int g = 0; g < 4; ++g) aA[g] = wredsum(aA[g]);
    if (lane == 0) {
      float gi = s * aA[0] + redB[0] + bdv[0];
      float gf = s * aA[1] + redB[1] + bdv[1];
      float gg = s * aA[2] + redB[2] + bdv[2];
      float go = s * aA[3] + redB[3] + bdv[3];
      dc = sigf(gf) * dc + sigf(gi) * tanhf(gg);
      float dhn = sigf(go) * tanhf(dc);
      __stcg(&d_dh[wt2][u], dhn);
      red_rel(&c_dh);
    }
  }

  // ---- final output: out[T-1] from final dh (in d_dh[0]) ----
  if (b == 0 && w == 1) {
    while (ld_acq(&c_dh) < 1024u * (unsigned)TT) __nanosleep(32);
    __syncwarp();
    float o = 0.f;
#pragma unroll
    for (int c = 0; c < 8; ++c) {
      float4 dv = __ldcg((const float4*)d_dh[0] + c * 32 + lane);
      o += dot4(__ldg((const float4*)Wout + c * 32 + lane), dv);
    }
    o = wredsum(o);
    if (lane == 0) out[TT - 1] = o + bout0;
  }
}

// ---------------- launch ----------------
extern "C" void kernel_launch(void* const* d_in, const int* in_sizes, int n_in,
                              void* d_out, int out_size) {
  const float* input_seq = (const float*)d_in[0];
  const float* W_ih_e = (const float*)d_in[2];
  const float* W_hh_e = (const float*)d_in[3];
  const float* b_ih_e = (const float*)d_in[4];
  const float* b_hh_e = (const float*)d_in[5];
  const float* W_attn = (const float*)d_in[6];
  const float* b_attn = (const float*)d_in[7];
  const float* W_ih_d = (const float*)d_in[8];
  const float* W_hh_d = (const float*)d_in[9];
  const float* b_ih_d = (const float*)d_in[10];
  const float* b_hh_d = (const float*)d_in[11];
  const float* W_out  = (const float*)d_in[12];
  const float* b_out  = (const float*)d_in[13];
  float* out = (float*)d_out;

  const int smem_bytes = SMEM_FLOATS * 4;  // 227392
  cudaFuncSetAttribute(lstm_persist, cudaFuncAttributeMaxDynamicSharedMemorySize, smem_bytes);

  init_state<<<8, 256>>>();
  build_comb<<<512, 256>>>(W_ih_d, W_hh_d, b_ih_d, b_hh_d);
  gemm_pre<<<dim3(TT / GBN, G / GBM), 256>>>(W_ih_e, input_seq, b_ih_e, b_hh_e);
  lstm_persist<<<NB, NT, smem_bytes>>>(W_hh_e, W_ih_d, W_attn, b_attn, W_out, b_out, out);
}

// round 6
// speedup vs baseline: 2.4716x; 1.0436x over previous
#include <cuda_runtime.h>
#include <cstdint>

#define TT 512
#define IDIM 512
#define H 1024
#define G 4096
#define NB 128
#define NT_ENC 256
#define NT_DEC 288

// ---------------- device scratch ----------------
__device__ __align__(16) float d_pre[(size_t)G * TT];       // W_ih_e@x_t + biases   [r][t]
__device__ __align__(16) float d_EH[(size_t)(TT + 1) * H];  // eh_t rows; row0 = 0
__device__ __align__(16) float d_DH[(size_t)(TT + 1) * H];  // dh_t rows; row0 = 0
__device__ unsigned c_e, c_d;                               // 1024 releases per step

__device__ __forceinline__ float sigf(float x) { return 1.f / (1.f + __expf(-x)); }
__device__ __forceinline__ float dot4(float4 a, float4 b) {
  return a.x * b.x + a.y * b.y + a.z * b.z + a.w * b.w;
}
__device__ __forceinline__ float wredsum(float v) {
#pragma unroll
  for (int o = 16; o; o >>= 1) v += __shfl_xor_sync(0xffffffffu, v, o);
  return v;
}
__device__ __forceinline__ float wredmax(float v) {
#pragma unroll
  for (int o = 16; o; o >>= 1) v = fmaxf(v, __shfl_xor_sync(0xffffffffu, v, o));
  return v;
}
__device__ __forceinline__ unsigned ld_acq(const unsigned* p) {
  unsigned v;
  asm volatile("ld.acquire.gpu.global.u32 %0, [%1];" : "=r"(v) : "l"(p) : "memory");
  return v;
}
__device__ __forceinline__ void red_rel(unsigned* p) {
  unsigned one = 1u;
  asm volatile("red.release.gpu.global.add.u32 [%0], %1;" :: "l"(p), "r"(one) : "memory");
}

// ---------------- init ----------------
__global__ void init_state() {
  int i = blockIdx.x * blockDim.x + threadIdx.x;
  if (i == 0) { c_e = 0; c_d = 0; }
  if (i < H) { d_EH[i] = 0.f; d_DH[i] = 0.f; }
}

// ---------------- R2-proven GEMM: d_pre[r][t] = W_ih_e@x_t + b_ih_e + b_hh_e ----------------
#define BM 64
#define BN 64
#define BK 32
__global__ void __launch_bounds__(256) gemm_pre(const float* __restrict__ A,
                                                const float* __restrict__ B,
                                                const float* __restrict__ bih,
                                                const float* __restrict__ bhh) {
  __shared__ float As[BK][BM + 1];
  __shared__ float Bs[BK][BN + 1];
  int tid = threadIdx.x;
  int r0 = blockIdx.y * BM;
  int t0 = blockIdx.x * BN;
  int tx = tid & 15, ty = tid >> 4;
  float acc[4][4] = {};
  for (int k0 = 0; k0 < IDIM; k0 += BK) {
#pragma unroll
    for (int i = 0; i < 8; ++i) {
      int lin = tid + i * 256;
      int m = lin >> 5, kk = lin & 31;
      As[kk][m] = A[(size_t)(r0 + m) * IDIM + k0 + kk];
      Bs[kk][m] = B[(size_t)(t0 + m) * IDIM + k0 + kk];
    }
    __syncthreads();
#pragma unroll
    for (int kk = 0; kk < BK; ++kk) {
      float a[4], bv[4];
#pragma unroll
      for (int j = 0; j < 4; ++j) { a[j] = As[kk][ty * 4 + j]; bv[j] = Bs[kk][tx * 4 + j]; }
#pragma unroll
      for (int i2 = 0; i2 < 4; ++i2)
#pragma unroll
        for (int j = 0; j < 4; ++j) acc[i2][j] += a[i2] * bv[j];
    }
    __syncthreads();
  }
#pragma unroll
  for (int i2 = 0; i2 < 4; ++i2) {
    int r = r0 + ty * 4 + i2;
    float bias = bih[r] + bhh[r];
#pragma unroll
    for (int j = 0; j < 4; ++j)
      d_pre[(size_t)r * TT + (t0 + tx * 4 + j)] = acc[i2][j] + bias;
  }
}

// ---------------- encoder persistent: eh_t for all t ----------------
__global__ void __launch_bounds__(NT_ENC, 1)
enc_persist(const float* __restrict__ Whh_e) {
  __shared__ __align__(16) float shEh[H];
  const int b = blockIdx.x, tid = threadIdx.x;
  const int w = tid >> 5, lane = tid & 31;
  const int u = b * 8 + w;

  float4 wreg[4][8];
#pragma unroll
  for (int g = 0; g < 4; ++g) {
    const float4* p = (const float4*)(Whh_e + (size_t)(u + g * H) * H);
#pragma unroll
    for (int c = 0; c < 8; ++c) wreg[g][c] = __ldg(p + c * 32 + lane);
  }

  float ec = 0.f;
  for (int t = 0; t < TT; ++t) {
    float pre_g[4];
    if (lane == 0) {
#pragma unroll
      for (int g = 0; g < 4; ++g) pre_g[g] = __ldg(&d_pre[(size_t)(u + g * H) * TT + t]);
    }
    if (tid == 0) {
      while (ld_acq(&c_e) < 1024u * (unsigned)t) __nanosleep(32);
    }
    __syncthreads();   // S1: all prior-step stores visible
    ((float4*)shEh)[tid] = __ldcg((const float4*)(d_EH + (size_t)t * H) + tid);
    __syncthreads();   // S2: staged

    float a[4] = {0.f, 0.f, 0.f, 0.f};
#pragma unroll
    for (int c = 0; c < 8; ++c) {
      float4 hv = ((const float4*)shEh)[c * 32 + lane];
#pragma unroll
      for (int g = 0; g < 4; ++g) a[g] += dot4(wreg[g][c], hv);
    }
#pragma unroll
    for (int g = 0; g < 4; ++g) a[g] = wredsum(a[g]);
    if (lane == 0) {
      float gi = a[0] + pre_g[0], gf = a[1] + pre_g[1];
      float gg = a[2] + pre_g[2], go = a[3] + pre_g[3];
      ec = sigf(gf) * ec + sigf(gi) * tanhf(gg);
      __stcg(&d_EH[(size_t)(t + 1) * H + u], sigf(go) * tanhf(ec));
      red_rel(&c_e);   // per-warp release of its own store (R2-proven)
    }
  }
}

// ---------------- decoder persistent ----------------
// smem: shWA [32][1024] = 128KB | shEh 4KB | shDh 4KB | shS
#define SMEM_DEC_FLOATS (32 * 1024 + 1024 + 1024 + 16)

__global__ void __launch_bounds__(NT_DEC, 1)
dec_persist(const float* __restrict__ Wihd, const float* __restrict__ Whhd,
            const float* __restrict__ bihd, const float* __restrict__ bhhd,
            const float* __restrict__ Wattn, const float* __restrict__ battn) {
  extern __shared__ __align__(16) float sh[];
  float* shWA = sh;                  // 32768 floats
  float* shEh = sh + 32 * 1024;      // 1024
  float* shDh = shEh + 1024;         // 1024
  float* shS  = shDh + 1024;         // 16

  const int b = blockIdx.x, tid = threadIdx.x;
  const int w = tid >> 5, lane = tid & 31;
  const int u = b * 8 + w;           // valid for w<8

  // W_A block rows -> smem: row jj = g*8+wv holds Wihd[(b*8+wv)+g*H][0:H]
  for (int i = tid; i < 32 * 256; i += NT_DEC) {
    int jj = i >> 8, c4 = i & 255;
    int g = jj >> 3, wv = jj & 7;
    ((float4*)shWA)[i] =
        __ldg((const float4*)(Wihd + ((size_t)(b * 8 + wv) + (size_t)g * H) * (2 * H)) + c4);
  }

  float4 wreg[4][8];                 // W_ih_d[:,H:] + W_hh_d rows (dh coefficients)
  float bd[4] = {0.f, 0.f, 0.f, 0.f};
  if (w < 8) {
#pragma unroll
    for (int g = 0; g < 4; ++g) {
      const int row = u + g * H;
      const float4* pA = (const float4*)(Wihd + (size_t)row * (2 * H) + H);
      const float4* pB = (const float4*)(Whhd + (size_t)row * H);
#pragma unroll
      for (int c = 0; c < 8; ++c) {
        float4 x = __ldg(pA + c * 32 + lane), y = __ldg(pB + c * 32 + lane);
        wreg[g][c] = make_float4(x.x + y.x, x.y + y.y, x.z + y.z, x.w + y.w);
      }
      bd[g] = __ldg(bihd + row) + __ldg(bhhd + row);
    }
  }
  float awreg[16];                   // warp 8: softmaxed attention weights
#pragma unroll
  for (int j = 0; j < 16; ++j) awreg[j] = 0.f;
  __syncthreads();

  float dc = 0.f;
  for (int t = 0; t < TT; ++t) {
    if (tid == 0) {
      while (ld_acq(&c_d) < 1024u * (unsigned)t) __nanosleep(32);
    }
    __syncthreads();   // S1
    if (tid < 256) {
      ((float4*)shEh)[tid] = __ldcg((const float4*)(d_EH + (size_t)(t + 1) * H) + tid);
      ((float4*)shDh)[tid] = __ldcg((const float4*)(d_DH + (size_t)t * H) + tid);
    }
    __syncthreads();   // S2

    float a[4] = {0.f, 0.f, 0.f, 0.f};
    float pa[4] = {0.f, 0.f, 0.f, 0.f};
    if (w < 8) {
#pragma unroll
      for (int c = 0; c < 8; ++c) {
        float4 dhc = ((const float4*)shDh)[c * 32 + lane];
        float4 ehc = ((const float4*)shEh)[c * 32 + lane];
#pragma unroll
        for (int g = 0; g < 4; ++g) {
          a[g]  += dot4(wreg[g][c], dhc);
          pa[g] += dot4(((const float4*)shWA)[(g * 8 + w) * 256 + c * 32 + lane], ehc);
        }
      }
#pragma unroll
      for (int g = 0; g < 4; ++g) { a[g] = wredsum(a[g]); pa[g] = wredsum(pa[g]); }
    } else {
      // full energy + register-resident softmax
      const float4* wrE = (const float4*)(Wattn + (size_t)t * (2 * H));
      const float4* wrD = wrE + 256;   // +H floats
      float e = 0.f;
#pragma unroll
      for (int c = 0; c < 8; ++c) {
        int idx = c * 32 + lane;
        e += dot4(__ldg(wrE + idx), ((const float4*)shEh)[idx]);
        e += dot4(__ldg(wrD + idx), ((const float4*)shDh)[idx]);
      }
      e = wredsum(e) + __ldg(&battn[t]);
      float vals[16];
      float m = -1e30f;
#pragma unroll
      for (int j = 0; j < 16; ++j) {
        float x = (j * 32 + lane == t) ? e : awreg[j];
        vals[j] = x;
        m = fmaxf(m, x);
      }
      m = wredmax(m);
      float ssum = 0.f;
#pragma unroll
      for (int j = 0; j < 16; ++j) { vals[j] = __expf(vals[j] - m); ssum += vals[j]; }
      ssum = wredsum(ssum);
      float inv = 1.f / ssum;
#pragma unroll
      for (int j = 0; j < 16; ++j) awreg[j] = vals[j] * inv;
      if (lane == 0) shS[0] = __expf(e - m) * inv;
    }
    __syncthreads();   // S3: shS published

    if (w < 8 && lane == 0) {
      float s = shS[0];
      float gi = s * pa[0] + a[0] + bd[0];
      float gf = s * pa[1] + a[1] + bd[1];
      float gg = s * pa[2] + a[2] + bd[2];
      float go = s * pa[3] + a[3] + bd[3];
      dc = sigf(gf) * dc + sigf(gi) * tanhf(gg);
      __stcg(&d_DH[(size_t)(t + 1) * H + u], sigf(go) * tanhf(dc));
      red_rel(&c_d);   // per-warp release of its own store
    }
  }
}

// ---------------- out[t] = Wout @ dh_{t+1} + bout ----------------
__global__ void out_final(const float* __restrict__ Wout, const float* __restrict__ bout,
                          float* __restrict__ out) {
  const int w = threadIdx.x >> 5, lane = threadIdx.x & 31;
  const int t = blockIdx.x * 8 + w;
  const float4* wo = (const float4*)Wout;
  const float4* dh = (const float4*)(d_DH + (size_t)(t + 1) * H);
  float o = 0.f;
#pragma unroll
  for (int c = 0; c < 8; ++c) o += dot4(__ldg(wo + c * 32 + lane), __ldcg(dh + c * 32 + lane));
  o = wredsum(o);
  if (lane == 0) out[t] = o + __ldg(bout);
}

// ---------------- launch ----------------
extern "C" void kernel_launch(void* const* d_in, const int* in_sizes, int n_in,
                              void* d_out, int out_size) {
  const float* input_seq = (const float*)d_in[0];
  const float* W_ih_e = (const float*)d_in[2];
  const float* W_hh_e = (const float*)d_in[3];
  const float* b_ih_e = (const float*)d_in[4];
  const float* b_hh_e = (const float*)d_in[5];
  const float* W_attn = (const float*)d_in[6];
  const float* b_attn = (const float*)d_in[7];
  const float* W_ih_d = (const float*)d_in[8];
  const float* W_hh_d = (const float*)d_in[9];
  const float* b_ih_d = (const float*)d_in[10];
  const float* b_hh_d = (const float*)d_in[11];
  const float* W_out  = (const float*)d_in[12];
  const float* b_out  = (const float*)d_in[13];
  float* out = (float*)d_out;

  const int smem_dec = SMEM_DEC_FLOATS * 4;   // ~139KB
  cudaFuncSetAttribute(dec_persist, cudaFuncAttributeMaxDynamicSharedMemorySize, smem_dec);

  init_state<<<4, 256>>>();
  gemm_pre<<<dim3(TT / BN, G / BM), 256>>>(W_ih_e, input_seq, b_ih_e, b_hh_e);
  enc_persist<<<NB, NT_ENC>>>(W_hh_e);
  dec_persist<<<NB, NT_DEC, smem_dec>>>(W_ih_d, W_hh_d, b_ih_d, b_hh_d, W_attn, b_attn);
  out_final<<<TT / 8, 256>>>(W_out, b_out, out);
}